// round 1
// baseline (speedup 1.0000x reference)
#include <cuda_runtime.h>
#include <cstdint>

#define N_ROWS 16384
#define OBS    1024
#define HID    2048
#define LAT    256
#define VOCAB  8192
#define HQ     4
#define LN_EPS 1e-5f

// ---------------- scratch (static device globals; no allocation) ----------------
__device__ float g_h[(size_t)N_ROWS * HID];          // h (pre/post LN), reused as dh
__device__ float g_resid[(size_t)N_ROWS * LAT];
__device__ float g_codesum[(size_t)N_ROWS * LAT];
__device__ float g_enorm[HQ * VOCAB];
__device__ unsigned long long g_argmin[N_ROWS];
__device__ float g_vq_partials[HQ * (N_ROWS / 8)];           // 4 * 2048
__device__ float g_recon_partials[(N_ROWS / 128) * (OBS / 128)]; // 1024

// monotonic float->uint map (total order incl. negatives)
__device__ __forceinline__ unsigned f2ord(float f) {
    unsigned u = __float_as_uint(f);
    return (u & 0x80000000u) ? ~u : (u | 0x80000000u);
}

// ---------------- generic 128x128x16 SGEMM with fused epilogues ----------------
// MODE 0: C = A@B + bias
// MODE 1: C = relu(A@B + bias)
// MODE 3: distance argmin: d = extra[col] - 2*acc ; packed (ord(d),col) atomicMin per row
// MODE 4: recon loss: sum((acc + bias - extra[row*N+col])^2) -> partials[block]
// BCOL:   B is column-major view (element (k,n) at B[n*K + k]) -- used for E^T
template<int MODE, bool BCOL>
__global__ void __launch_bounds__(256) gemm_kernel(
    int M, int N, int K,
    const float* __restrict__ A, const float* __restrict__ B,
    const float* __restrict__ bias, float* __restrict__ C,
    const float* __restrict__ extra,
    unsigned long long* __restrict__ argmin,
    float* __restrict__ partials)
{
    __shared__ float As[16][128];
    __shared__ float Bs[16][128];
    __shared__ float red[256];

    const int tid  = threadIdx.x;
    const int row0 = blockIdx.y * 128;
    const int n0   = blockIdx.x * 128;
    const int ty   = tid >> 4;   // 0..15
    const int tx   = tid & 15;   // 0..15

    float acc[8][8];
#pragma unroll
    for (int i = 0; i < 8; i++)
#pragma unroll
        for (int j = 0; j < 8; j++) acc[i][j] = 0.f;

    const int ar = tid >> 2;          // 0..63
    const int ac = (tid & 3) << 2;    // 0,4,8,12
    const int br = tid >> 5;          // 0..7
    const int bc = (tid & 31) << 2;   // 0..124

    for (int kt = 0; kt < K; kt += 16) {
        // A tile (row-major [M,K]) -> transposed into As[k][m]
#pragma unroll
        for (int it = 0; it < 2; ++it) {
            const float4 v = *(const float4*)&A[(size_t)(row0 + ar + it * 64) * K + kt + ac];
            As[ac + 0][ar + it * 64] = v.x;
            As[ac + 1][ar + it * 64] = v.y;
            As[ac + 2][ar + it * 64] = v.z;
            As[ac + 3][ar + it * 64] = v.w;
        }
        if (BCOL) {
            // B is E [N_rows=VOCAB, K=LAT] row-major; we need Bs[k][n] = E[n][k]
#pragma unroll
            for (int it = 0; it < 2; ++it) {
                const float4 v = *(const float4*)&B[(size_t)(n0 + ar + it * 64) * K + kt + ac];
                Bs[ac + 0][ar + it * 64] = v.x;
                Bs[ac + 1][ar + it * 64] = v.y;
                Bs[ac + 2][ar + it * 64] = v.z;
                Bs[ac + 3][ar + it * 64] = v.w;
            }
        } else {
#pragma unroll
            for (int it = 0; it < 2; ++it) {
                const float4 v = *(const float4*)&B[(size_t)(kt + br + it * 8) * N + n0 + bc];
                *(float4*)&Bs[br + it * 8][bc] = v;
            }
        }
        __syncthreads();
#pragma unroll
        for (int k = 0; k < 16; ++k) {
            float ra[8], rb[8];
#pragma unroll
            for (int i = 0; i < 8; i++) ra[i] = As[k][ty * 8 + i];
#pragma unroll
            for (int j = 0; j < 8; j++) rb[j] = Bs[k][tx * 8 + j];
#pragma unroll
            for (int i = 0; i < 8; i++)
#pragma unroll
                for (int j = 0; j < 8; j++)
                    acc[i][j] = fmaf(ra[i], rb[j], acc[i][j]);
        }
        __syncthreads();
    }

    if (MODE == 0 || MODE == 1) {
#pragma unroll
        for (int i = 0; i < 8; i++) {
            const size_t row = (size_t)(row0 + ty * 8 + i);
#pragma unroll
            for (int j4 = 0; j4 < 8; j4 += 4) {
                const int col = n0 + tx * 8 + j4;
                float4 v;
                v.x = acc[i][j4 + 0] + bias[col + 0];
                v.y = acc[i][j4 + 1] + bias[col + 1];
                v.z = acc[i][j4 + 2] + bias[col + 2];
                v.w = acc[i][j4 + 3] + bias[col + 3];
                if (MODE == 1) {
                    v.x = fmaxf(v.x, 0.f); v.y = fmaxf(v.y, 0.f);
                    v.z = fmaxf(v.z, 0.f); v.w = fmaxf(v.w, 0.f);
                }
                *(float4*)&C[row * N + col] = v;
            }
        }
    } else if (MODE == 3) {
#pragma unroll
        for (int i = 0; i < 8; i++) {
            const int row = row0 + ty * 8 + i;
            float best = __int_as_float(0x7f800000);
            int bi = 0;
#pragma unroll
            for (int j = 0; j < 8; j++) {
                const int col = n0 + tx * 8 + j;
                const float d = fmaf(-2.f, acc[i][j], extra[col]);
                if (d < best) { best = d; bi = col; }
            }
            unsigned long long key =
                ((unsigned long long)f2ord(best) << 32) | (unsigned)bi;
#pragma unroll
            for (int off = 8; off > 0; off >>= 1) {
                unsigned long long o = __shfl_down_sync(0xffffffffu, key, off, 16);
                if (o < key) key = o;
            }
            if (tx == 0) atomicMin(&argmin[row], key);
        }
    } else if (MODE == 4) {
        float lsum = 0.f;
#pragma unroll
        for (int i = 0; i < 8; i++) {
            const size_t row = (size_t)(row0 + ty * 8 + i);
#pragma unroll
            for (int j = 0; j < 8; j++) {
                const int col = n0 + tx * 8 + j;
                const float v = acc[i][j] + bias[col];
                const float e = v - extra[row * N + col];
                lsum = fmaf(e, e, lsum);
            }
        }
        red[tid] = lsum;
        __syncthreads();
#pragma unroll
        for (int s = 128; s > 0; s >>= 1) {
            if (tid < s) red[tid] += red[tid + s];
            __syncthreads();
        }
        if (tid == 0) partials[blockIdx.y * gridDim.x + blockIdx.x] = red[0];
    }
}

// ---------------- LayerNorm + ReLU (one block per row of 2048) ----------------
__global__ void __launch_bounds__(256) ln_relu_kernel(
    float* __restrict__ h, const float* __restrict__ g, const float* __restrict__ b)
{
    const int row = blockIdx.x;
    float* hr = h + (size_t)row * HID;
    float vals[8];
    float s = 0.f, s2 = 0.f;
#pragma unroll
    for (int i = 0; i < 8; i++) {
        const float v = hr[threadIdx.x + i * 256];
        vals[i] = v;
        s += v;
        s2 = fmaf(v, v, s2);
    }
    __shared__ float sh1[256], sh2[256];
    sh1[threadIdx.x] = s; sh2[threadIdx.x] = s2;
    __syncthreads();
    for (int st = 128; st > 0; st >>= 1) {
        if (threadIdx.x < st) {
            sh1[threadIdx.x] += sh1[threadIdx.x + st];
            sh2[threadIdx.x] += sh2[threadIdx.x + st];
        }
        __syncthreads();
    }
    const float mu  = sh1[0] * (1.f / HID);
    const float var = sh2[0] * (1.f / HID) - mu * mu;
    const float inv = rsqrtf(var + LN_EPS);
#pragma unroll
    for (int i = 0; i < 8; i++) {
        const int col = threadIdx.x + i * 256;
        const float v = (vals[i] - mu) * inv * g[col] + b[col];
        hr[col] = fmaxf(v, 0.f);
    }
}

// ---------------- codebook row norms ----------------
__global__ void __launch_bounds__(256) enorm_kernel(
    const float* __restrict__ cb, float* __restrict__ en)
{
    const int gw   = (blockIdx.x * 256 + threadIdx.x) >> 5;  // codebook row id
    const int lane = threadIdx.x & 31;
    const float* e = cb + (size_t)gw * LAT;
    float s = 0.f;
#pragma unroll
    for (int c = lane; c < LAT; c += 32) s = fmaf(e[c], e[c], s);
#pragma unroll
    for (int off = 16; off > 0; off >>= 1) s += __shfl_down_sync(0xffffffffu, s, off);
    if (lane == 0) en[gw] = s;
}

__global__ void init_argmin_kernel(unsigned long long* __restrict__ a) {
    a[blockIdx.x * 256 + threadIdx.x] = ~0ull;
}

// ---------------- gather q, VQ loss partial, update resid/code_sum ----------------
template<bool FIRST>
__global__ void __launch_bounds__(256) vq_gather_kernel(
    const float* __restrict__ E, float* __restrict__ resid,
    float* __restrict__ codesum, const unsigned long long* __restrict__ argmin,
    float* __restrict__ partials)
{
    const int warp = threadIdx.x >> 5;
    const int lane = threadIdx.x & 31;
    const int row  = blockIdx.x * 8 + warp;
    const unsigned idx = (unsigned)(argmin[row] & 0xffffffffu);
    const float* q = E + (size_t)idx * LAT;
    float* rr = resid   + (size_t)row * LAT;
    float* cs = codesum + (size_t)row * LAT;
    float lsum = 0.f;
#pragma unroll
    for (int c = lane * 4; c < LAT; c += 128) {
        const float4 qv = *(const float4*)&q[c];
        const float4 rv = *(const float4*)&rr[c];
        const float dx = qv.x - rv.x, dy = qv.y - rv.y;
        const float dz = qv.z - rv.z, dw = qv.w - rv.w;
        lsum += dx * dx + dy * dy + dz * dz + dw * dw;
        *(float4*)&rr[c] = make_float4(rv.x - qv.x, rv.y - qv.y, rv.z - qv.z, rv.w - qv.w);
        if (FIRST) {
            *(float4*)&cs[c] = qv;
        } else {
            float4 cv = *(float4*)&cs[c];
            cv.x += qv.x; cv.y += qv.y; cv.z += qv.z; cv.w += qv.w;
            *(float4*)&cs[c] = cv;
        }
    }
#pragma unroll
    for (int off = 16; off > 0; off >>= 1) lsum += __shfl_down_sync(0xffffffffu, lsum, off);
    __shared__ float ws[8];
    if (lane == 0) ws[warp] = lsum;
    __syncthreads();
    if (threadIdx.x == 0) {
        float t = 0.f;
#pragma unroll
        for (int w = 0; w < 8; w++) t += ws[w];
        partials[blockIdx.x] = t;
    }
}

// ---------------- final deterministic reduction ----------------
__global__ void __launch_bounds__(256) final_kernel(
    const float* __restrict__ vqp, const float* __restrict__ rp, float* __restrict__ out)
{
    __shared__ float sv[256], sr[256];
    float a = 0.f, b = 0.f;
    for (int i = threadIdx.x; i < HQ * (N_ROWS / 8); i += 256) a += vqp[i];
    for (int i = threadIdx.x; i < (N_ROWS / 128) * (OBS / 128); i += 256) b += rp[i];
    sv[threadIdx.x] = a; sr[threadIdx.x] = b;
    __syncthreads();
    for (int s = 128; s > 0; s >>= 1) {
        if (threadIdx.x < s) {
            sv[threadIdx.x] += sv[threadIdx.x + s];
            sr[threadIdx.x] += sr[threadIdx.x + s];
        }
        __syncthreads();
    }
    if (threadIdx.x == 0) {
        out[0] = 1.5f * sv[0] / ((float)N_ROWS * (float)LAT)
               + 0.5f * sr[0] / ((float)N_ROWS * (float)OBS);
    }
}

// ---------------- host launcher ----------------
extern "C" void kernel_launch(void* const* d_in, const int* in_sizes, int n_in,
                              void* d_out, int out_size)
{
    const float* x   = (const float*)d_in[0];
    const float* cb  = (const float*)d_in[1];
    const float* ew1 = (const float*)d_in[2];
    const float* eb1 = (const float*)d_in[3];
    const float* lng = (const float*)d_in[4];
    const float* lnb = (const float*)d_in[5];
    const float* ew2 = (const float*)d_in[6];
    const float* eb2 = (const float*)d_in[7];
    const float* dw1 = (const float*)d_in[8];
    const float* db1 = (const float*)d_in[9];
    const float* dw2 = (const float*)d_in[10];
    const float* db2 = (const float*)d_in[11];
    float* out = (float*)d_out;

    float *p_h, *p_resid, *p_codesum, *p_enorm, *p_vqp, *p_rp;
    unsigned long long* p_arg;
    cudaGetSymbolAddress((void**)&p_h,       g_h);
    cudaGetSymbolAddress((void**)&p_resid,   g_resid);
    cudaGetSymbolAddress((void**)&p_codesum, g_codesum);
    cudaGetSymbolAddress((void**)&p_enorm,   g_enorm);
    cudaGetSymbolAddress((void**)&p_arg,     g_argmin);
    cudaGetSymbolAddress((void**)&p_vqp,     g_vq_partials);
    cudaGetSymbolAddress((void**)&p_rp,      g_recon_partials);

    // codebook row norms
    enorm_kernel<<<HQ * VOCAB / 8, 256>>>(cb, p_enorm);

    // encoder: h_pre = x @ W1 + b1
    gemm_kernel<0, false><<<dim3(HID / 128, N_ROWS / 128), 256>>>(
        N_ROWS, HID, OBS, x, ew1, eb1, p_h, nullptr, nullptr, nullptr);
    // LN + ReLU in place
    ln_relu_kernel<<<N_ROWS, 256>>>(p_h, lng, lnb);
    // latent (== initial resid) = h @ W2 + b2
    gemm_kernel<0, false><<<dim3(LAT / 128, N_ROWS / 128), 256>>>(
        N_ROWS, LAT, HID, p_h, ew2, eb2, p_resid, nullptr, nullptr, nullptr);

    // residual VQ levels
    for (int l = 0; l < HQ; ++l) {
        init_argmin_kernel<<<N_ROWS / 256, 256>>>(p_arg);
        gemm_kernel<3, true><<<dim3(VOCAB / 128, N_ROWS / 128), 256>>>(
            N_ROWS, VOCAB, LAT, p_resid, cb + (size_t)l * VOCAB * LAT,
            nullptr, nullptr, p_enorm + l * VOCAB, p_arg, nullptr);
        if (l == 0)
            vq_gather_kernel<true><<<N_ROWS / 8, 256>>>(
                cb + (size_t)l * VOCAB * LAT, p_resid, p_codesum, p_arg,
                p_vqp + l * (N_ROWS / 8));
        else
            vq_gather_kernel<false><<<N_ROWS / 8, 256>>>(
                cb + (size_t)l * VOCAB * LAT, p_resid, p_codesum, p_arg,
                p_vqp + l * (N_ROWS / 8));
    }

    // decoder: dh = relu(code_sum @ dW1 + db1)  (reuse g_h)
    gemm_kernel<1, false><<<dim3(HID / 128, N_ROWS / 128), 256>>>(
        N_ROWS, HID, LAT, p_codesum, dw1, db1, p_h, nullptr, nullptr, nullptr);
    // recon = dh @ dW2 + db2, fused 0.5*MSE vs x partials
    gemm_kernel<4, false><<<dim3(OBS / 128, N_ROWS / 128), 256>>>(
        N_ROWS, OBS, HID, p_h, dw2, db2, nullptr, x, nullptr, p_rp);

    final_kernel<<<1, 256>>>(p_vqp, p_rp, out);
}

// round 3
// speedup vs baseline: 7.9030x; 7.9030x over previous
#include <cuda_runtime.h>
#include <cuda_bf16.h>
#include <cstdint>

#define N_ROWS 16384
#define OBS    1024
#define HID    2048
#define LAT    256
#define VOCAB  8192
#define HQ     4
#define LN_EPS 1e-5f

// ---------------- tiling ----------------
#define TILE_M 128
#define TILE_N 128
#define TILE_K 64                       // bf16 elems per K step (128 bytes/row)
#define STAGE_BYTES (TILE_M*128 + TILE_N*128)   // 32768
#define SMEM_AUX 0                      // 128 floats
#define SMEM_STAGE0 1024
#define DYN_SMEM (SMEM_STAGE0 + 2*STAGE_BYTES)  // 66560
#define A_STAGE_OFF(s) (SMEM_STAGE0 + (s)*STAGE_BYTES)
#define B_STAGE_OFF(s) (A_STAGE_OFF(s) + TILE_M*128)

enum { EPI_H = 0, EPI_LAT = 1, EPI_DIST = 2, EPI_RELU = 3, EPI_MSE = 4 };

// ---------------- scratch ----------------
__device__ __align__(1024) __nv_bfloat16 g_xb[(size_t)N_ROWS * OBS];
__device__ __align__(1024) __nv_bfloat16 g_hb[(size_t)N_ROWS * HID];
__device__ __align__(1024) __nv_bfloat16 g_residb[(size_t)N_ROWS * LAT];
__device__ __align__(1024) __nv_bfloat16 g_csb[(size_t)N_ROWS * LAT];
__device__ __align__(1024) __nv_bfloat16 g_cbb[(size_t)HQ * VOCAB * LAT];
__device__ __align__(1024) __nv_bfloat16 g_w1t[(size_t)HID * OBS];
__device__ __align__(1024) __nv_bfloat16 g_w2t[(size_t)LAT * HID];
__device__ __align__(1024) __nv_bfloat16 g_dw1t[(size_t)HID * LAT];
__device__ __align__(1024) __nv_bfloat16 g_dw2t[(size_t)OBS * HID];
__device__ float g_h[(size_t)N_ROWS * HID];
__device__ float g_resid[(size_t)N_ROWS * LAT];
__device__ float g_codesum[(size_t)N_ROWS * LAT];
__device__ float g_enorm[HQ * VOCAB];
__device__ unsigned long long g_argmin[N_ROWS];
__device__ float g_vq_partials[HQ * (N_ROWS / 8)];
#define RP_COUNT ((N_ROWS / TILE_M) * (OBS / TILE_N))
__device__ float g_recon_partials[RP_COUNT];

// ---------------- helpers ----------------
__device__ __forceinline__ uint32_t smem_u32(const void* p) {
    uint32_t a;
    asm("{ .reg .u64 t; cvta.to.shared.u64 t, %1; cvt.u32.u64 %0, t; }" : "=r"(a) : "l"(p));
    return a;
}
#define SWZ(o) ((o) ^ (((o) >> 3) & 0x70))
#define CP_ASYNC16(dst, src) \
    asm volatile("cp.async.cg.shared.global [%0], [%1], 16;" :: "r"((uint32_t)(dst)), "l"(src))
#define CP_COMMIT() asm volatile("cp.async.commit_group;" ::: "memory")

__device__ __forceinline__ void ldsm_x4(uint32_t addr, uint32_t& r0, uint32_t& r1,
                                        uint32_t& r2, uint32_t& r3) {
    asm volatile("ldmatrix.sync.aligned.m8n8.x4.shared.b16 {%0,%1,%2,%3}, [%4];"
                 : "=r"(r0), "=r"(r1), "=r"(r2), "=r"(r3) : "r"(addr));
}
__device__ __forceinline__ void mma_bf16(float* d, uint32_t a0, uint32_t a1,
                                         uint32_t a2, uint32_t a3,
                                         uint32_t b0, uint32_t b1) {
    asm volatile("mma.sync.aligned.m16n8k16.row.col.f32.bf16.bf16.f32 "
                 "{%0,%1,%2,%3}, {%4,%5,%6,%7}, {%8,%9}, {%0,%1,%2,%3};"
                 : "+f"(d[0]), "+f"(d[1]), "+f"(d[2]), "+f"(d[3])
                 : "r"(a0), "r"(a1), "r"(a2), "r"(a3), "r"(b0), "r"(b1));
}
__device__ __forceinline__ unsigned f2ord(float f) {
    unsigned u = __float_as_uint(f);
    return (u & 0x80000000u) ? ~u : (u | 0x80000000u);
}

// fill one pipeline stage: A tile [128 x 128B] + B tile [128 x 128B]
__device__ __forceinline__ void fill_stage(
    uint32_t smem_base, int s, const __nv_bfloat16* __restrict__ A,
    const __nv_bfloat16* __restrict__ B, int K, int m0, int n0, int chunk, int tid)
{
    const int kt = chunk * TILE_K;
    const uint32_t a_s = smem_base + A_STAGE_OFF(s);
    const uint32_t b_s = smem_base + B_STAGE_OFF(s);
#pragma unroll
    for (int i = 0; i < 4; i++) {
        const int c = tid + i * 256;
        const int row = c >> 3;
        const int o = (c & 7) * 16;
        CP_ASYNC16(a_s + SWZ(row * 128 + o),
                   (const char*)(A + (size_t)(m0 + row) * K + kt) + o);
    }
#pragma unroll
    for (int i = 0; i < 4; i++) {
        const int c = tid + i * 256;
        const int row = c >> 3;
        const int o = (c & 7) * 16;
        CP_ASYNC16(b_s + SWZ(row * 128 + o),
                   (const char*)(B + (size_t)(n0 + row) * K + kt) + o);
    }
}

// ---------------- bf16 mma.sync GEMM with fused epilogues ----------------
// C = A[M,K] @ B[N,K]^T ; 8 warps, warp tile 32x64 (4 warps in M, 2 in N)
template<int EPI>
__global__ void __launch_bounds__(256) tc_gemm(
    const __nv_bfloat16* __restrict__ A, const __nv_bfloat16* __restrict__ B, int K,
    const float* __restrict__ aux_vec,          // bias or enorm (per col)
    float* __restrict__ out_f32,
    __nv_bfloat16* __restrict__ out_bf16,
    const float* __restrict__ xref,
    unsigned long long* __restrict__ argmin,
    float* __restrict__ partials)
{
    extern __shared__ __align__(1024) char smem[];
    const uint32_t smem_base = smem_u32(smem);
    const int tid = threadIdx.x;
    const int lane = tid & 31, wid = tid >> 5;
    const int wm = wid >> 1, wn = wid & 1;
    const int m0 = blockIdx.y * TILE_M;
    const int n0 = blockIdx.x * TILE_N;
    const int Nn = gridDim.x * TILE_N;
    const int niter = K >> 6;

    float* aux = (float*)(smem + SMEM_AUX);
    if (tid < 128) aux[tid] = aux_vec[n0 + tid];

    float acc[2][8][4];
#pragma unroll
    for (int fi = 0; fi < 2; fi++)
#pragma unroll
        for (int nf = 0; nf < 8; nf++)
#pragma unroll
            for (int q = 0; q < 4; q++) acc[fi][nf][q] = 0.f;

    // per-thread ldmatrix lane geometry
    const int a_row_l = wm * 32 + (lane & 15);       // + fi*16
    const int a_kb_l  = (lane >> 4) * 16;
    const int b_row_l = wn * 64 + (lane & 7) + ((lane >> 4) & 1) * 8;  // + nf2*16
    const int b_kb_l  = (lane & 8) ? 16 : 0;

    fill_stage(smem_base, 0, A, B, K, m0, n0, 0, tid); CP_COMMIT();
    fill_stage(smem_base, 1, A, B, K, m0, n0, 1, tid); CP_COMMIT();

    for (int it = 0; it < niter; ++it) {
        const int s = it & 1;
        if (it + 2 <= niter) { asm volatile("cp.async.wait_group 1;" ::: "memory"); }
        else                 { asm volatile("cp.async.wait_group 0;" ::: "memory"); }
        __syncthreads();

        const uint32_t a_s = smem_base + A_STAGE_OFF(s);
        const uint32_t b_s = smem_base + B_STAGE_OFF(s);
#pragma unroll
        for (int k = 0; k < 4; ++k) {
            const int kb = k * 32;
            uint32_t a[2][4];
#pragma unroll
            for (int fi = 0; fi < 2; fi++) {
                const int row = a_row_l + fi * 16;
                ldsm_x4(a_s + SWZ(row * 128 + kb + a_kb_l),
                        a[fi][0], a[fi][1], a[fi][2], a[fi][3]);
            }
            uint32_t b[8][2];
#pragma unroll
            for (int nf2 = 0; nf2 < 4; nf2++) {
                const int row = b_row_l + nf2 * 16;
                ldsm_x4(b_s + SWZ(row * 128 + kb + b_kb_l),
                        b[nf2*2][0], b[nf2*2][1], b[nf2*2+1][0], b[nf2*2+1][1]);
            }
#pragma unroll
            for (int fi = 0; fi < 2; fi++)
#pragma unroll
                for (int nf = 0; nf < 8; nf++)
                    mma_bf16(acc[fi][nf], a[fi][0], a[fi][1], a[fi][2], a[fi][3],
                             b[nf][0], b[nf][1]);
        }

        if (it + 2 < niter) {
            __syncthreads();
            fill_stage(smem_base, s, A, B, K, m0, n0, it + 2, tid);
            CP_COMMIT();
        }
    }

    // ---------------- epilogue ----------------
    const int tr = lane >> 2;           // 0..7
    const int tc = (lane & 3) * 2;      // 0,2,4,6

    if (EPI == EPI_DIST) {
#pragma unroll
        for (int fi = 0; fi < 2; fi++) {
#pragma unroll
            for (int half = 0; half < 2; half++) {
                float best = __int_as_float(0x7f800000);
                int bi = 0;
#pragma unroll
                for (int nf = 0; nf < 8; nf++) {
                    const int col = wn * 64 + nf * 8 + tc;
                    float d0 = fmaf(-2.f, acc[fi][nf][half*2+0], aux[col]);
                    float d1 = fmaf(-2.f, acc[fi][nf][half*2+1], aux[col+1]);
                    if (d0 < best) { best = d0; bi = n0 + col; }
                    if (d1 < best) { best = d1; bi = n0 + col + 1; }
                }
                unsigned long long key =
                    ((unsigned long long)f2ord(best) << 32) | (unsigned)bi;
                unsigned long long o;
                o = __shfl_xor_sync(0xffffffffu, key, 1); if (o < key) key = o;
                o = __shfl_xor_sync(0xffffffffu, key, 2); if (o < key) key = o;
                if ((lane & 3) == 0) {
                    const int row = m0 + wm * 32 + fi * 16 + tr + half * 8;
                    atomicMin(&argmin[row], key);
                }
            }
        }
    } else if (EPI == EPI_MSE) {
        float ls = 0.f;
#pragma unroll
        for (int fi = 0; fi < 2; fi++)
#pragma unroll
            for (int half = 0; half < 2; half++) {
                const size_t row = (size_t)(m0 + wm * 32 + fi * 16 + tr + half * 8);
#pragma unroll
                for (int nf = 0; nf < 8; nf++) {
                    const int col = wn * 64 + nf * 8 + tc;
                    const float2 xv = *(const float2*)&xref[row * OBS + n0 + col];
                    float e0 = acc[fi][nf][half*2+0] + aux[col]   - xv.x;
                    float e1 = acc[fi][nf][half*2+1] + aux[col+1] - xv.y;
                    ls = fmaf(e0, e0, ls);
                    ls = fmaf(e1, e1, ls);
                }
            }
        __syncthreads();
        float* red = (float*)(smem + SMEM_STAGE0);
        red[tid] = ls;
        __syncthreads();
#pragma unroll
        for (int st = 128; st > 0; st >>= 1) {
            if (tid < st) red[tid] += red[tid + st];
            __syncthreads();
        }
        if (tid == 0) partials[blockIdx.y * gridDim.x + blockIdx.x] = red[0];
    } else {
#pragma unroll
        for (int fi = 0; fi < 2; fi++)
#pragma unroll
            for (int half = 0; half < 2; half++) {
                const size_t row = (size_t)(m0 + wm * 32 + fi * 16 + tr + half * 8);
#pragma unroll
                for (int nf = 0; nf < 8; nf++) {
                    const int col = wn * 64 + nf * 8 + tc;
                    float v0 = acc[fi][nf][half*2+0] + aux[col];
                    float v1 = acc[fi][nf][half*2+1] + aux[col+1];
                    if (EPI == EPI_RELU) { v0 = fmaxf(v0, 0.f); v1 = fmaxf(v1, 0.f); }
                    if (EPI == EPI_H || EPI == EPI_LAT)
                        *(float2*)&out_f32[row * Nn + n0 + col] = make_float2(v0, v1);
                    if (EPI == EPI_LAT || EPI == EPI_RELU) {
                        __nv_bfloat162 p = __float22bfloat162_rn(make_float2(v0, v1));
                        *(__nv_bfloat162*)&out_bf16[row * Nn + n0 + col] = p;
                    }
                }
            }
    }
}

// ---------------- conversion / transpose ----------------
__global__ void __launch_bounds__(256) to_bf16_kernel(
    const float* __restrict__ in, __nv_bfloat16* __restrict__ out)
{
    const size_t i = (size_t)blockIdx.x * 256 + threadIdx.x;
    const float4 v = ((const float4*)in)[i];
    ((__nv_bfloat162*)out)[2 * i + 0] = __float22bfloat162_rn(make_float2(v.x, v.y));
    ((__nv_bfloat162*)out)[2 * i + 1] = __float22bfloat162_rn(make_float2(v.z, v.w));
}

__global__ void __launch_bounds__(256) transpose_bf16_kernel(
    const float* __restrict__ in, __nv_bfloat16* __restrict__ out, int R, int C)
{
    __shared__ float t[32][33];
    const int c0 = blockIdx.x * 32, r0 = blockIdx.y * 32;
    const int tx = threadIdx.x, ty = threadIdx.y;
#pragma unroll
    for (int i = 0; i < 32; i += 8)
        t[ty + i][tx] = in[(size_t)(r0 + ty + i) * C + c0 + tx];
    __syncthreads();
#pragma unroll
    for (int i = 0; i < 32; i += 8)
        out[(size_t)(c0 + ty + i) * R + r0 + tx] = __float2bfloat16_rn(t[tx][ty + i]);
}

// ---------------- LayerNorm + ReLU -> bf16 ----------------
__global__ void __launch_bounds__(256) ln_relu_kernel(
    const float* __restrict__ h, __nv_bfloat16* __restrict__ hb,
    const float* __restrict__ g, const float* __restrict__ b)
{
    const int row = blockIdx.x;
    const float* hr = h + (size_t)row * HID;
    __nv_bfloat16* ho = hb + (size_t)row * HID;
    float vals[8];
    float s = 0.f, s2 = 0.f;
#pragma unroll
    for (int i = 0; i < 8; i++) {
        const float v = hr[threadIdx.x + i * 256];
        vals[i] = v;
        s += v;
        s2 = fmaf(v, v, s2);
    }
    __shared__ float sh1[256], sh2[256];
    sh1[threadIdx.x] = s; sh2[threadIdx.x] = s2;
    __syncthreads();
    for (int st = 128; st > 0; st >>= 1) {
        if (threadIdx.x < st) {
            sh1[threadIdx.x] += sh1[threadIdx.x + st];
            sh2[threadIdx.x] += sh2[threadIdx.x + st];
        }
        __syncthreads();
    }
    const float mu  = sh1[0] * (1.f / HID);
    const float var = sh2[0] * (1.f / HID) - mu * mu;
    const float inv = rsqrtf(var + LN_EPS);
#pragma unroll
    for (int i = 0; i < 8; i++) {
        const int col = threadIdx.x + i * 256;
        const float v = (vals[i] - mu) * inv * g[col] + b[col];
        ho[col] = __float2bfloat16_rn(fmaxf(v, 0.f));
    }
}

// ---------------- codebook row norms (fp32) ----------------
__global__ void __launch_bounds__(256) enorm_kernel(
    const float* __restrict__ cb, float* __restrict__ en)
{
    const int gw   = (blockIdx.x * 256 + threadIdx.x) >> 5;
    const int lane = threadIdx.x & 31;
    const float* e = cb + (size_t)gw * LAT;
    float s = 0.f;
#pragma unroll
    for (int c = lane; c < LAT; c += 32) s = fmaf(e[c], e[c], s);
#pragma unroll
    for (int off = 16; off > 0; off >>= 1) s += __shfl_down_sync(0xffffffffu, s, off);
    if (lane == 0) en[gw] = s;
}

__global__ void init_argmin_kernel(unsigned long long* __restrict__ a) {
    a[blockIdx.x * 256 + threadIdx.x] = ~0ull;
}

// ---------------- VQ gather + loss partial + resid/codesum update ----------------
template<bool FIRST, bool LAST>
__global__ void __launch_bounds__(256) vq_gather_kernel(
    const float* __restrict__ E, float* __restrict__ resid,
    __nv_bfloat16* __restrict__ residb,
    float* __restrict__ codesum, __nv_bfloat16* __restrict__ csb,
    const unsigned long long* __restrict__ argmin, float* __restrict__ partials)
{
    const int warp = threadIdx.x >> 5;
    const int lane = threadIdx.x & 31;
    const int row  = blockIdx.x * 8 + warp;
    const unsigned idx = (unsigned)(argmin[row] & 0xffffffffu);
    const float* q = E + (size_t)idx * LAT;
    float* rr = resid   + (size_t)row * LAT;
    float* cs = codesum + (size_t)row * LAT;
    __nv_bfloat16* rb = residb + (size_t)row * LAT;
    __nv_bfloat16* cbp = csb   + (size_t)row * LAT;
    float lsum = 0.f;
#pragma unroll
    for (int c = lane * 4; c < LAT; c += 128) {
        const float4 qv = *(const float4*)&q[c];
        const float4 rv = *(const float4*)&rr[c];
        const float dx = qv.x - rv.x, dy = qv.y - rv.y;
        const float dz = qv.z - rv.z, dw = qv.w - rv.w;
        lsum += dx * dx + dy * dy + dz * dz + dw * dw;
        const float4 nr = make_float4(rv.x - qv.x, rv.y - qv.y, rv.z - qv.z, rv.w - qv.w);
        *(float4*)&rr[c] = nr;
        float4 cv;
        if (FIRST) cv = qv;
        else {
            cv = *(float4*)&cs[c];
            cv.x += qv.x; cv.y += qv.y; cv.z += qv.z; cv.w += qv.w;
        }
        *(float4*)&cs[c] = cv;
        if (LAST) {
            ((__nv_bfloat162*)&cbp[c])[0] = __float22bfloat162_rn(make_float2(cv.x, cv.y));
            ((__nv_bfloat162*)&cbp[c])[1] = __float22bfloat162_rn(make_float2(cv.z, cv.w));
        } else {
            ((__nv_bfloat162*)&rb[c])[0] = __float22bfloat162_rn(make_float2(nr.x, nr.y));
            ((__nv_bfloat162*)&rb[c])[1] = __float22bfloat162_rn(make_float2(nr.z, nr.w));
        }
    }
#pragma unroll
    for (int off = 16; off > 0; off >>= 1) lsum += __shfl_down_sync(0xffffffffu, lsum, off);
    __shared__ float ws[8];
    if (lane == 0) ws[warp] = lsum;
    __syncthreads();
    if (threadIdx.x == 0) {
        float t = 0.f;
#pragma unroll
        for (int w = 0; w < 8; w++) t += ws[w];
        partials[blockIdx.x] = t;
    }
}

// ---------------- final deterministic reduction ----------------
__global__ void __launch_bounds__(256) final_kernel(
    const float* __restrict__ vqp, const float* __restrict__ rp, float* __restrict__ out)
{
    __shared__ float sv[256], sr[256];
    float a = 0.f, b = 0.f;
    for (int i = threadIdx.x; i < HQ * (N_ROWS / 8); i += 256) a += vqp[i];
    for (int i = threadIdx.x; i < RP_COUNT; i += 256) b += rp[i];
    sv[threadIdx.x] = a; sr[threadIdx.x] = b;
    __syncthreads();
    for (int s = 128; s > 0; s >>= 1) {
        if (threadIdx.x < s) {
            sv[threadIdx.x] += sv[threadIdx.x + s];
            sr[threadIdx.x] += sr[threadIdx.x + s];
        }
        __syncthreads();
    }
    if (threadIdx.x == 0) {
        out[0] = 1.5f * sv[0] / ((float)N_ROWS * (float)LAT)
               + 0.5f * sr[0] / ((float)N_ROWS * (float)OBS);
    }
}

// ---------------- host launcher ----------------
extern "C" void kernel_launch(void* const* d_in, const int* in_sizes, int n_in,
                              void* d_out, int out_size)
{
    const float* x   = (const float*)d_in[0];
    const float* cb  = (const float*)d_in[1];
    const float* ew1 = (const float*)d_in[2];
    const float* eb1 = (const float*)d_in[3];
    const float* lng = (const float*)d_in[4];
    const float* lnb = (const float*)d_in[5];
    const float* ew2 = (const float*)d_in[6];
    const float* eb2 = (const float*)d_in[7];
    const float* dw1 = (const float*)d_in[8];
    const float* db1 = (const float*)d_in[9];
    const float* dw2 = (const float*)d_in[10];
    const float* db2 = (const float*)d_in[11];
    float* out = (float*)d_out;

    float *p_h, *p_resid, *p_codesum, *p_enorm, *p_vqp, *p_rp;
    unsigned long long* p_arg;
    __nv_bfloat16 *p_xb, *p_hb, *p_residb, *p_csb, *p_cbb, *p_w1t, *p_w2t, *p_dw1t, *p_dw2t;
    cudaGetSymbolAddress((void**)&p_h,       g_h);
    cudaGetSymbolAddress((void**)&p_resid,   g_resid);
    cudaGetSymbolAddress((void**)&p_codesum, g_codesum);
    cudaGetSymbolAddress((void**)&p_enorm,   g_enorm);
    cudaGetSymbolAddress((void**)&p_arg,     g_argmin);
    cudaGetSymbolAddress((void**)&p_vqp,     g_vq_partials);
    cudaGetSymbolAddress((void**)&p_rp,      g_recon_partials);
    cudaGetSymbolAddress((void**)&p_xb,      g_xb);
    cudaGetSymbolAddress((void**)&p_hb,      g_hb);
    cudaGetSymbolAddress((void**)&p_residb,  g_residb);
    cudaGetSymbolAddress((void**)&p_csb,     g_csb);
    cudaGetSymbolAddress((void**)&p_cbb,     g_cbb);
    cudaGetSymbolAddress((void**)&p_w1t,     g_w1t);
    cudaGetSymbolAddress((void**)&p_w2t,     g_w2t);
    cudaGetSymbolAddress((void**)&p_dw1t,    g_dw1t);
    cudaGetSymbolAddress((void**)&p_dw2t,    g_dw2t);

    cudaFuncSetAttribute(tc_gemm<EPI_H>,    cudaFuncAttributeMaxDynamicSharedMemorySize, DYN_SMEM);
    cudaFuncSetAttribute(tc_gemm<EPI_LAT>,  cudaFuncAttributeMaxDynamicSharedMemorySize, DYN_SMEM);
    cudaFuncSetAttribute(tc_gemm<EPI_DIST>, cudaFuncAttributeMaxDynamicSharedMemorySize, DYN_SMEM);
    cudaFuncSetAttribute(tc_gemm<EPI_RELU>, cudaFuncAttributeMaxDynamicSharedMemorySize, DYN_SMEM);
    cudaFuncSetAttribute(tc_gemm<EPI_MSE>,  cudaFuncAttributeMaxDynamicSharedMemorySize, DYN_SMEM);

    // conversions
    to_bf16_kernel<<<(N_ROWS * OBS) / 1024, 256>>>(x, p_xb);
    to_bf16_kernel<<<(HQ * VOCAB * LAT) / 1024, 256>>>(cb, p_cbb);
    transpose_bf16_kernel<<<dim3(HID / 32, OBS / 32), dim3(32, 8)>>>(ew1, p_w1t, OBS, HID);
    transpose_bf16_kernel<<<dim3(LAT / 32, HID / 32), dim3(32, 8)>>>(ew2, p_w2t, HID, LAT);
    transpose_bf16_kernel<<<dim3(HID / 32, LAT / 32), dim3(32, 8)>>>(dw1, p_dw1t, LAT, HID);
    transpose_bf16_kernel<<<dim3(OBS / 32, HID / 32), dim3(32, 8)>>>(dw2, p_dw2t, HID, OBS);
    enorm_kernel<<<HQ * VOCAB / 8, 256>>>(cb, p_enorm);

    // encoder
    tc_gemm<EPI_H><<<dim3(HID / TILE_N, N_ROWS / TILE_M), 256, DYN_SMEM>>>(
        p_xb, p_w1t, OBS, eb1, p_h, nullptr, nullptr, nullptr, nullptr);
    ln_relu_kernel<<<N_ROWS, 256>>>(p_h, p_hb, lng, lnb);
    tc_gemm<EPI_LAT><<<dim3(LAT / TILE_N, N_ROWS / TILE_M), 256, DYN_SMEM>>>(
        p_hb, p_w2t, HID, eb2, p_resid, p_residb, nullptr, nullptr, nullptr);

    // residual VQ levels
    for (int l = 0; l < HQ; ++l) {
        init_argmin_kernel<<<N_ROWS / 256, 256>>>(p_arg);
        tc_gemm<EPI_DIST><<<dim3(VOCAB / TILE_N, N_ROWS / TILE_M), 256, DYN_SMEM>>>(
            p_residb, p_cbb + (size_t)l * VOCAB * LAT, LAT,
            p_enorm + l * VOCAB, nullptr, nullptr, nullptr, p_arg, nullptr);
        const float* El = cb + (size_t)l * VOCAB * LAT;
        float* vp = p_vqp + l * (N_ROWS / 8);
        if (l == 0)
            vq_gather_kernel<true, false><<<N_ROWS / 8, 256>>>(
                El, p_resid, p_residb, p_codesum, p_csb, p_arg, vp);
        else if (l == HQ - 1)
            vq_gather_kernel<false, true><<<N_ROWS / 8, 256>>>(
                El, p_resid, p_residb, p_codesum, p_csb, p_arg, vp);
        else
            vq_gather_kernel<false, false><<<N_ROWS / 8, 256>>>(
                El, p_resid, p_residb, p_codesum, p_csb, p_arg, vp);
    }

    // decoder (g_hb reused as dh bf16)
    tc_gemm<EPI_RELU><<<dim3(HID / TILE_N, N_ROWS / TILE_M), 256, DYN_SMEM>>>(
        p_csb, p_dw1t, LAT, db1, nullptr, p_hb, nullptr, nullptr, nullptr);
    tc_gemm<EPI_MSE><<<dim3(OBS / TILE_N, N_ROWS / TILE_M), 256, DYN_SMEM>>>(
        p_hb, p_dw2t, HID, db2, nullptr, nullptr, x, nullptr, p_rp);

    final_kernel<<<1, 256>>>(p_vqp, p_rp, out);
}

// round 4
// speedup vs baseline: 8.0100x; 1.0135x over previous
#include <cuda_runtime.h>
#include <cuda_bf16.h>
#include <cstdint>

#define N_ROWS 16384
#define OBS    1024
#define HID    2048
#define LAT    256
#define VOCAB  8192
#define HQ     4
#define LN_EPS 1e-5f

// ---------------- tiling ----------------
#define TILE_M 128
#define TILE_N 128
#define TILE_K 64                       // bf16 elems per K step (128 bytes/row)
#define NSTAGE 3
#define STAGE_BYTES (TILE_M*128 + TILE_N*128)   // 32768
#define SMEM_AUX 0                      // 128 floats
#define SMEM_STAGE0 1024
#define DYN_SMEM (SMEM_STAGE0 + NSTAGE*STAGE_BYTES)  // 99328
#define A_STAGE_OFF(s) (SMEM_STAGE0 + (s)*STAGE_BYTES)
#define B_STAGE_OFF(s) (A_STAGE_OFF(s) + TILE_M*128)

enum { EPI_H = 0, EPI_LAT = 1, EPI_DIST = 2, EPI_RELU = 3, EPI_MSE = 4 };

// ---------------- scratch ----------------
__device__ __align__(1024) __nv_bfloat16 g_xb[(size_t)N_ROWS * OBS];
__device__ __align__(1024) __nv_bfloat16 g_hb[(size_t)N_ROWS * HID];
__device__ __align__(1024) __nv_bfloat16 g_residb[(size_t)N_ROWS * LAT];
__device__ __align__(1024) __nv_bfloat16 g_csb[(size_t)N_ROWS * LAT];
__device__ __align__(1024) __nv_bfloat16 g_cbb[(size_t)HQ * VOCAB * LAT];
__device__ __align__(1024) __nv_bfloat16 g_w1t[(size_t)HID * OBS];
__device__ __align__(1024) __nv_bfloat16 g_w2t[(size_t)LAT * HID];
__device__ __align__(1024) __nv_bfloat16 g_dw1t[(size_t)HID * LAT];
__device__ __align__(1024) __nv_bfloat16 g_dw2t[(size_t)OBS * HID];
__device__ float g_h[(size_t)N_ROWS * HID];
__device__ float g_resid[(size_t)N_ROWS * LAT];
__device__ float g_codesum[(size_t)N_ROWS * LAT];
__device__ float g_enorm[HQ * VOCAB];
__device__ unsigned long long g_argmin[HQ * N_ROWS];
__device__ float g_vq_partials[HQ * (N_ROWS / 8)];
#define RP_COUNT ((N_ROWS / TILE_M) * (OBS / TILE_N))
__device__ float g_recon_partials[RP_COUNT];

// ---------------- helpers ----------------
__device__ __forceinline__ uint32_t smem_u32(const void* p) {
    uint32_t a;
    asm("{ .reg .u64 t; cvta.to.shared.u64 t, %1; cvt.u32.u64 %0, t; }" : "=r"(a) : "l"(p));
    return a;
}
#define SWZ(o) ((o) ^ (((o) >> 3) & 0x70))
#define CP_ASYNC16(dst, src) \
    asm volatile("cp.async.cg.shared.global [%0], [%1], 16;" :: "r"((uint32_t)(dst)), "l"(src))
#define CP_COMMIT() asm volatile("cp.async.commit_group;" ::: "memory")

__device__ __forceinline__ void ldsm_x4(uint32_t addr, uint32_t& r0, uint32_t& r1,
                                        uint32_t& r2, uint32_t& r3) {
    asm volatile("ldmatrix.sync.aligned.m8n8.x4.shared.b16 {%0,%1,%2,%3}, [%4];"
                 : "=r"(r0), "=r"(r1), "=r"(r2), "=r"(r3) : "r"(addr));
}
__device__ __forceinline__ void mma_bf16(float* d, uint32_t a0, uint32_t a1,
                                         uint32_t a2, uint32_t a3,
                                         uint32_t b0, uint32_t b1) {
    asm volatile("mma.sync.aligned.m16n8k16.row.col.f32.bf16.bf16.f32 "
                 "{%0,%1,%2,%3}, {%4,%5,%6,%7}, {%8,%9}, {%0,%1,%2,%3};"
                 : "+f"(d[0]), "+f"(d[1]), "+f"(d[2]), "+f"(d[3])
                 : "r"(a0), "r"(a1), "r"(a2), "r"(a3), "r"(b0), "r"(b1));
}
__device__ __forceinline__ unsigned f2ord(float f) {
    unsigned u = __float_as_uint(f);
    return (u & 0x80000000u) ? ~u : (u | 0x80000000u);
}

// fill one pipeline stage: A tile [128 x 128B] + B tile [128 x 128B]
__device__ __forceinline__ void fill_stage(
    uint32_t smem_base, int s, const __nv_bfloat16* __restrict__ A,
    const __nv_bfloat16* __restrict__ B, int K, int m0, int n0, int chunk, int tid)
{
    const int kt = chunk * TILE_K;
    const uint32_t a_s = smem_base + A_STAGE_OFF(s);
    const uint32_t b_s = smem_base + B_STAGE_OFF(s);
#pragma unroll
    for (int i = 0; i < 4; i++) {
        const int c = tid + i * 256;
        const int row = c >> 3;
        const int o = (c & 7) * 16;
        CP_ASYNC16(a_s + SWZ(row * 128 + o),
                   (const char*)(A + (size_t)(m0 + row) * K + kt) + o);
    }
#pragma unroll
    for (int i = 0; i < 4; i++) {
        const int c = tid + i * 256;
        const int row = c >> 3;
        const int o = (c & 7) * 16;
        CP_ASYNC16(b_s + SWZ(row * 128 + o),
                   (const char*)(B + (size_t)(n0 + row) * K + kt) + o);
    }
}

// ---------------- bf16 mma.sync GEMM with fused epilogues ----------------
// C = A[M,K] @ B[N,K]^T ; 8 warps, warp tile 32x64 (4 warps in M, 2 in N)
template<int EPI>
__global__ void __launch_bounds__(256) tc_gemm(
    const __nv_bfloat16* __restrict__ A, const __nv_bfloat16* __restrict__ B, int K,
    const float* __restrict__ aux_vec,          // bias or enorm (per col)
    float* __restrict__ out_f32,
    __nv_bfloat16* __restrict__ out_bf16,
    const float* __restrict__ xref,
    unsigned long long* __restrict__ argmin,
    float* __restrict__ partials)
{
    extern __shared__ __align__(1024) char smem[];
    const uint32_t smem_base = smem_u32(smem);
    const int tid = threadIdx.x;
    const int lane = tid & 31, wid = tid >> 5;
    const int wm = wid >> 1, wn = wid & 1;
    const int m0 = blockIdx.y * TILE_M;
    const int n0 = blockIdx.x * TILE_N;
    const int Nn = gridDim.x * TILE_N;
    const int niter = K >> 6;

    float* aux = (float*)(smem + SMEM_AUX);
    if (tid < 128) aux[tid] = aux_vec[n0 + tid];

    float acc[2][8][4];
#pragma unroll
    for (int fi = 0; fi < 2; fi++)
#pragma unroll
        for (int nf = 0; nf < 8; nf++)
#pragma unroll
            for (int q = 0; q < 4; q++) acc[fi][nf][q] = 0.f;

    // per-thread ldmatrix lane geometry
    const int a_row_l = wm * 32 + (lane & 15);       // + fi*16
    const int a_kb_l  = (lane >> 4) * 16;
    const int b_row_l = wn * 64 + (lane & 7) + ((lane >> 4) & 1) * 8;  // + nf2*16
    const int b_kb_l  = (lane & 8) ? 16 : 0;

    // prologue: prefetch chunks 0,1
    fill_stage(smem_base, 0, A, B, K, m0, n0, 0, tid); CP_COMMIT();
    fill_stage(smem_base, 1, A, B, K, m0, n0, 1, tid); CP_COMMIT();

    int s = 0;
    for (int it = 0; it < niter; ++it) {
        if (it < niter - 1) { asm volatile("cp.async.wait_group 1;" ::: "memory"); }
        else                { asm volatile("cp.async.wait_group 0;" ::: "memory"); }
        __syncthreads();   // chunk `it` visible to all; all warps done with stage being refilled

        if (it + 2 < niter) {
            int fs = s + 2; if (fs >= NSTAGE) fs -= NSTAGE;
            fill_stage(smem_base, fs, A, B, K, m0, n0, it + 2, tid);
            CP_COMMIT();
        }

        const uint32_t a_s = smem_base + A_STAGE_OFF(s);
        const uint32_t b_s = smem_base + B_STAGE_OFF(s);
#pragma unroll
        for (int k = 0; k < 4; ++k) {
            const int kb = k * 32;
            uint32_t a[2][4];
#pragma unroll
            for (int fi = 0; fi < 2; fi++) {
                const int row = a_row_l + fi * 16;
                ldsm_x4(a_s + SWZ(row * 128 + kb + a_kb_l),
                        a[fi][0], a[fi][1], a[fi][2], a[fi][3]);
            }
            uint32_t b[8][2];
#pragma unroll
            for (int nf2 = 0; nf2 < 4; nf2++) {
                const int row = b_row_l + nf2 * 16;
                ldsm_x4(b_s + SWZ(row * 128 + kb + b_kb_l),
                        b[nf2*2][0], b[nf2*2][1], b[nf2*2+1][0], b[nf2*2+1][1]);
            }
#pragma unroll
            for (int fi = 0; fi < 2; fi++)
#pragma unroll
                for (int nf = 0; nf < 8; nf++)
                    mma_bf16(acc[fi][nf], a[fi][0], a[fi][1], a[fi][2], a[fi][3],
                             b[nf][0], b[nf][1]);
        }
        if (++s >= NSTAGE) s = 0;
    }

    // ---------------- epilogue ----------------
    const int tr = lane >> 2;           // 0..7
    const int tc = (lane & 3) * 2;      // 0,2,4,6

    if (EPI == EPI_DIST) {
#pragma unroll
        for (int fi = 0; fi < 2; fi++) {
#pragma unroll
            for (int half = 0; half < 2; half++) {
                float best = __int_as_float(0x7f800000);
                int bi = 0;
#pragma unroll
                for (int nf = 0; nf < 8; nf++) {
                    const int col = wn * 64 + nf * 8 + tc;
                    float d0 = fmaf(-2.f, acc[fi][nf][half*2+0], aux[col]);
                    float d1 = fmaf(-2.f, acc[fi][nf][half*2+1], aux[col+1]);
                    if (d0 < best) { best = d0; bi = n0 + col; }
                    if (d1 < best) { best = d1; bi = n0 + col + 1; }
                }
                unsigned long long key =
                    ((unsigned long long)f2ord(best) << 32) | (unsigned)bi;
                unsigned long long o;
                o = __shfl_xor_sync(0xffffffffu, key, 1); if (o < key) key = o;
                o = __shfl_xor_sync(0xffffffffu, key, 2); if (o < key) key = o;
                if ((lane & 3) == 0) {
                    const int row = m0 + wm * 32 + fi * 16 + tr + half * 8;
                    atomicMin(&argmin[row], key);
                }
            }
        }
    } else if (EPI == EPI_MSE) {
        float ls = 0.f;
#pragma unroll
        for (int fi = 0; fi < 2; fi++)
#pragma unroll
            for (int half = 0; half < 2; half++) {
                const size_t row = (size_t)(m0 + wm * 32 + fi * 16 + tr + half * 8);
#pragma unroll
                for (int nf = 0; nf < 8; nf++) {
                    const int col = wn * 64 + nf * 8 + tc;
                    const float2 xv = *(const float2*)&xref[row * OBS + n0 + col];
                    float e0 = acc[fi][nf][half*2+0] + aux[col]   - xv.x;
                    float e1 = acc[fi][nf][half*2+1] + aux[col+1] - xv.y;
                    ls = fmaf(e0, e0, ls);
                    ls = fmaf(e1, e1, ls);
                }
            }
        __syncthreads();
        float* red = (float*)(smem + SMEM_STAGE0);
        red[tid] = ls;
        __syncthreads();
#pragma unroll
        for (int st = 128; st > 0; st >>= 1) {
            if (tid < st) red[tid] += red[tid + st];
            __syncthreads();
        }
        if (tid == 0) partials[blockIdx.y * gridDim.x + blockIdx.x] = red[0];
    } else {
#pragma unroll
        for (int fi = 0; fi < 2; fi++)
#pragma unroll
            for (int half = 0; half < 2; half++) {
                const size_t row = (size_t)(m0 + wm * 32 + fi * 16 + tr + half * 8);
#pragma unroll
                for (int nf = 0; nf < 8; nf++) {
                    const int col = wn * 64 + nf * 8 + tc;
                    float v0 = acc[fi][nf][half*2+0] + aux[col];
                    float v1 = acc[fi][nf][half*2+1] + aux[col+1];
                    if (EPI == EPI_RELU) { v0 = fmaxf(v0, 0.f); v1 = fmaxf(v1, 0.f); }
                    if (EPI == EPI_H || EPI == EPI_LAT)
                        *(float2*)&out_f32[row * Nn + n0 + col] = make_float2(v0, v1);
                    if (EPI == EPI_LAT || EPI == EPI_RELU) {
                        __nv_bfloat162 p = __float22bfloat162_rn(make_float2(v0, v1));
                        *(__nv_bfloat162*)&out_bf16[row * Nn + n0 + col] = p;
                    }
                }
            }
    }
}

// ---------------- conversion / transpose ----------------
__global__ void __launch_bounds__(256) to_bf16_kernel(
    const float* __restrict__ in, __nv_bfloat16* __restrict__ out)
{
    const size_t i = (size_t)blockIdx.x * 256 + threadIdx.x;
    const float4 v = ((const float4*)in)[i];
    ((__nv_bfloat162*)out)[2 * i + 0] = __float22bfloat162_rn(make_float2(v.x, v.y));
    ((__nv_bfloat162*)out)[2 * i + 1] = __float22bfloat162_rn(make_float2(v.z, v.w));
}

__global__ void __launch_bounds__(256) transpose_bf16_kernel(
    const float* __restrict__ in, __nv_bfloat16* __restrict__ out, int R, int C)
{
    __shared__ float t[32][33];
    const int c0 = blockIdx.x * 32, r0 = blockIdx.y * 32;
    const int tx = threadIdx.x, ty = threadIdx.y;
#pragma unroll
    for (int i = 0; i < 32; i += 8)
        t[ty + i][tx] = in[(size_t)(r0 + ty + i) * C + c0 + tx];
    __syncthreads();
#pragma unroll
    for (int i = 0; i < 32; i += 8)
        out[(size_t)(c0 + ty + i) * R + r0 + tx] = __float2bfloat16_rn(t[tx][ty + i]);
}

// ---------------- LayerNorm + ReLU -> bf16 ----------------
__global__ void __launch_bounds__(256) ln_relu_kernel(
    const float* __restrict__ h, __nv_bfloat16* __restrict__ hb,
    const float* __restrict__ g, const float* __restrict__ b)
{
    const int row = blockIdx.x;
    const float* hr = h + (size_t)row * HID;
    __nv_bfloat16* ho = hb + (size_t)row * HID;
    float vals[8];
    float s = 0.f, s2 = 0.f;
#pragma unroll
    for (int i = 0; i < 8; i++) {
        const float v = hr[threadIdx.x + i * 256];
        vals[i] = v;
        s += v;
        s2 = fmaf(v, v, s2);
    }
    __shared__ float sh1[256], sh2[256];
    sh1[threadIdx.x] = s; sh2[threadIdx.x] = s2;
    __syncthreads();
    for (int st = 128; st > 0; st >>= 1) {
        if (threadIdx.x < st) {
            sh1[threadIdx.x] += sh1[threadIdx.x + st];
            sh2[threadIdx.x] += sh2[threadIdx.x + st];
        }
        __syncthreads();
    }
    const float mu  = sh1[0] * (1.f / HID);
    const float var = sh2[0] * (1.f / HID) - mu * mu;
    const float inv = rsqrtf(var + LN_EPS);
#pragma unroll
    for (int i = 0; i < 8; i++) {
        const int col = threadIdx.x + i * 256;
        const float v = (vals[i] - mu) * inv * g[col] + b[col];
        ho[col] = __float2bfloat16_rn(fmaxf(v, 0.f));
    }
}

// ---------------- codebook row norms (fp32) ----------------
__global__ void __launch_bounds__(256) enorm_kernel(
    const float* __restrict__ cb, float* __restrict__ en)
{
    const int gw   = (blockIdx.x * 256 + threadIdx.x) >> 5;
    const int lane = threadIdx.x & 31;
    const float* e = cb + (size_t)gw * LAT;
    float s = 0.f;
#pragma unroll
    for (int c = lane; c < LAT; c += 32) s = fmaf(e[c], e[c], s);
#pragma unroll
    for (int off = 16; off > 0; off >>= 1) s += __shfl_down_sync(0xffffffffu, s, off);
    if (lane == 0) en[gw] = s;
}

__global__ void init_argmin_kernel(unsigned long long* __restrict__ a) {
    a[(size_t)blockIdx.x * 256 + threadIdx.x] = ~0ull;
}

// ---------------- VQ gather + loss partial + resid/codesum update ----------------
template<bool FIRST, bool LAST>
__global__ void __launch_bounds__(256) vq_gather_kernel(
    const float* __restrict__ E, float* __restrict__ resid,
    __nv_bfloat16* __restrict__ residb,
    float* __restrict__ codesum, __nv_bfloat16* __restrict__ csb,
    const unsigned long long* __restrict__ argmin, float* __restrict__ partials)
{
    const int warp = threadIdx.x >> 5;
    const int lane = threadIdx.x & 31;
    const int row  = blockIdx.x * 8 + warp;
    const unsigned idx = (unsigned)(argmin[row] & 0xffffffffu);
    const float* q = E + (size_t)idx * LAT;
    float* rr = resid   + (size_t)row * LAT;
    float* cs = codesum + (size_t)row * LAT;
    __nv_bfloat16* rb = residb + (size_t)row * LAT;
    __nv_bfloat16* cbp = csb   + (size_t)row * LAT;
    float lsum = 0.f;
#pragma unroll
    for (int c = lane * 4; c < LAT; c += 128) {
        const float4 qv = *(const float4*)&q[c];
        const float4 rv = *(const float4*)&rr[c];
        const float dx = qv.x - rv.x, dy = qv.y - rv.y;
        const float dz = qv.z - rv.z, dw = qv.w - rv.w;
        lsum += dx * dx + dy * dy + dz * dz + dw * dw;
        const float4 nr = make_float4(rv.x - qv.x, rv.y - qv.y, rv.z - qv.z, rv.w - qv.w);
        *(float4*)&rr[c] = nr;
        float4 cv;
        if (FIRST) cv = qv;
        else {
            cv = *(float4*)&cs[c];
            cv.x += qv.x; cv.y += qv.y; cv.z += qv.z; cv.w += qv.w;
        }
        *(float4*)&cs[c] = cv;
        if (LAST) {
            ((__nv_bfloat162*)&cbp[c])[0] = __float22bfloat162_rn(make_float2(cv.x, cv.y));
            ((__nv_bfloat162*)&cbp[c])[1] = __float22bfloat162_rn(make_float2(cv.z, cv.w));
        } else {
            ((__nv_bfloat162*)&rb[c])[0] = __float22bfloat162_rn(make_float2(nr.x, nr.y));
            ((__nv_bfloat162*)&rb[c])[1] = __float22bfloat162_rn(make_float2(nr.z, nr.w));
        }
    }
#pragma unroll
    for (int off = 16; off > 0; off >>= 1) lsum += __shfl_down_sync(0xffffffffu, lsum, off);
    __shared__ float ws[8];
    if (lane == 0) ws[warp] = lsum;
    __syncthreads();
    if (threadIdx.x == 0) {
        float t = 0.f;
#pragma unroll
        for (int w = 0; w < 8; w++) t += ws[w];
        partials[blockIdx.x] = t;
    }
}

// ---------------- final deterministic reduction ----------------
__global__ void __launch_bounds__(256) final_kernel(
    const float* __restrict__ vqp, const float* __restrict__ rp, float* __restrict__ out)
{
    __shared__ float sv[256], sr[256];
    float a = 0.f, b = 0.f;
    for (int i = threadIdx.x; i < HQ * (N_ROWS / 8); i += 256) a += vqp[i];
    for (int i = threadIdx.x; i < RP_COUNT; i += 256) b += rp[i];
    sv[threadIdx.x] = a; sr[threadIdx.x] = b;
    __syncthreads();
    for (int s = 128; s > 0; s >>= 1) {
        if (threadIdx.x < s) {
            sv[threadIdx.x] += sv[threadIdx.x + s];
            sr[threadIdx.x] += sr[threadIdx.x + s];
        }
        __syncthreads();
    }
    if (threadIdx.x == 0) {
        out[0] = 1.5f * sv[0] / ((float)N_ROWS * (float)LAT)
               + 0.5f * sr[0] / ((float)N_ROWS * (float)OBS);
    }
}

// ---------------- host launcher ----------------
extern "C" void kernel_launch(void* const* d_in, const int* in_sizes, int n_in,
                              void* d_out, int out_size)
{
    const float* x   = (const float*)d_in[0];
    const float* cb  = (const float*)d_in[1];
    const float* ew1 = (const float*)d_in[2];
    const float* eb1 = (const float*)d_in[3];
    const float* lng = (const float*)d_in[4];
    const float* lnb = (const float*)d_in[5];
    const float* ew2 = (const float*)d_in[6];
    const float* eb2 = (const float*)d_in[7];
    const float* dw1 = (const float*)d_in[8];
    const float* db1 = (const float*)d_in[9];
    const float* dw2 = (const float*)d_in[10];
    const float* db2 = (const float*)d_in[11];
    float* out = (float*)d_out;

    float *p_h, *p_resid, *p_codesum, *p_enorm, *p_vqp, *p_rp;
    unsigned long long* p_arg;
    __nv_bfloat16 *p_xb, *p_hb, *p_residb, *p_csb, *p_cbb, *p_w1t, *p_w2t, *p_dw1t, *p_dw2t;
    cudaGetSymbolAddress((void**)&p_h,       g_h);
    cudaGetSymbolAddress((void**)&p_resid,   g_resid);
    cudaGetSymbolAddress((void**)&p_codesum, g_codesum);
    cudaGetSymbolAddress((void**)&p_enorm,   g_enorm);
    cudaGetSymbolAddress((void**)&p_arg,     g_argmin);
    cudaGetSymbolAddress((void**)&p_vqp,     g_vq_partials);
    cudaGetSymbolAddress((void**)&p_rp,      g_recon_partials);
    cudaGetSymbolAddress((void**)&p_xb,      g_xb);
    cudaGetSymbolAddress((void**)&p_hb,      g_hb);
    cudaGetSymbolAddress((void**)&p_residb,  g_residb);
    cudaGetSymbolAddress((void**)&p_csb,     g_csb);
    cudaGetSymbolAddress((void**)&p_cbb,     g_cbb);
    cudaGetSymbolAddress((void**)&p_w1t,     g_w1t);
    cudaGetSymbolAddress((void**)&p_w2t,     g_w2t);
    cudaGetSymbolAddress((void**)&p_dw1t,    g_dw1t);
    cudaGetSymbolAddress((void**)&p_dw2t,    g_dw2t);

    cudaFuncSetAttribute(tc_gemm<EPI_H>,    cudaFuncAttributeMaxDynamicSharedMemorySize, DYN_SMEM);
    cudaFuncSetAttribute(tc_gemm<EPI_LAT>,  cudaFuncAttributeMaxDynamicSharedMemorySize, DYN_SMEM);
    cudaFuncSetAttribute(tc_gemm<EPI_DIST>, cudaFuncAttributeMaxDynamicSharedMemorySize, DYN_SMEM);
    cudaFuncSetAttribute(tc_gemm<EPI_RELU>, cudaFuncAttributeMaxDynamicSharedMemorySize, DYN_SMEM);
    cudaFuncSetAttribute(tc_gemm<EPI_MSE>,  cudaFuncAttributeMaxDynamicSharedMemorySize, DYN_SMEM);

    // conversions + one-shot argmin init for all levels
    init_argmin_kernel<<<HQ * N_ROWS / 256, 256>>>(p_arg);
    to_bf16_kernel<<<(N_ROWS * OBS) / 1024, 256>>>(x, p_xb);
    to_bf16_kernel<<<(HQ * VOCAB * LAT) / 1024, 256>>>(cb, p_cbb);
    transpose_bf16_kernel<<<dim3(HID / 32, OBS / 32), dim3(32, 8)>>>(ew1, p_w1t, OBS, HID);
    transpose_bf16_kernel<<<dim3(LAT / 32, HID / 32), dim3(32, 8)>>>(ew2, p_w2t, HID, LAT);
    transpose_bf16_kernel<<<dim3(HID / 32, LAT / 32), dim3(32, 8)>>>(dw1, p_dw1t, LAT, HID);
    transpose_bf16_kernel<<<dim3(OBS / 32, HID / 32), dim3(32, 8)>>>(dw2, p_dw2t, HID, OBS);
    enorm_kernel<<<HQ * VOCAB / 8, 256>>>(cb, p_enorm);

    // encoder
    tc_gemm<EPI_H><<<dim3(HID / TILE_N, N_ROWS / TILE_M), 256, DYN_SMEM>>>(
        p_xb, p_w1t, OBS, eb1, p_h, nullptr, nullptr, nullptr, nullptr);
    ln_relu_kernel<<<N_ROWS, 256>>>(p_h, p_hb, lng, lnb);
    tc_gemm<EPI_LAT><<<dim3(LAT / TILE_N, N_ROWS / TILE_M), 256, DYN_SMEM>>>(
        p_hb, p_w2t, HID, eb2, p_resid, p_residb, nullptr, nullptr, nullptr);

    // residual VQ levels
    for (int l = 0; l < HQ; ++l) {
        tc_gemm<EPI_DIST><<<dim3(VOCAB / TILE_N, N_ROWS / TILE_M), 256, DYN_SMEM>>>(
            p_residb, p_cbb + (size_t)l * VOCAB * LAT, LAT,
            p_enorm + l * VOCAB, nullptr, nullptr, nullptr, p_arg + l * N_ROWS, nullptr);
        const float* El = cb + (size_t)l * VOCAB * LAT;
        float* vp = p_vqp + l * (N_ROWS / 8);
        if (l == 0)
            vq_gather_kernel<true, false><<<N_ROWS / 8, 256>>>(
                El, p_resid, p_residb, p_codesum, p_csb, p_arg + l * N_ROWS, vp);
        else if (l == HQ - 1)
            vq_gather_kernel<false, true><<<N_ROWS / 8, 256>>>(
                El, p_resid, p_residb, p_codesum, p_csb, p_arg + l * N_ROWS, vp);
        else
            vq_gather_kernel<false, false><<<N_ROWS / 8, 256>>>(
                El, p_resid, p_residb, p_codesum, p_csb, p_arg + l * N_ROWS, vp);
    }

    // decoder (g_hb reused as dh bf16)
    tc_gemm<EPI_RELU><<<dim3(HID / TILE_N, N_ROWS / TILE_M), 256, DYN_SMEM>>>(
        p_csb, p_dw1t, LAT, db1, nullptr, p_hb, nullptr, nullptr, nullptr);
    tc_gemm<EPI_MSE><<<dim3(OBS / TILE_N, N_ROWS / TILE_M), 256, DYN_SMEM>>>(
        p_hb, p_dw2t, HID, db2, nullptr, nullptr, x, nullptr, p_rp);

    final_kernel<<<1, 256>>>(p_vqp, p_rp, out);
}